// round 1
// baseline (speedup 1.0000x reference)
#include <cuda_runtime.h>

// Problem constants
#define B_   32
#define S_   1024
#define V_   300
#define KIN  316      // PRETRAIN(300) + FLAG(16)
#define PRE_ 300
#define FLG_ 16
#define RD_  200      // ROLE_D

// Tiling
#define BM 64
#define BN 64
#define BK 16
#define TM 4
#define TN 4
#define NTHREADS 256

// Scratch for proj: [B, S, RD] fp32 = 32*1024*200*4 = 26.2 MB (static, no alloc)
__device__ float g_proj[B_ * S_ * RD_];

// ---------------------------------------------------------------------------
// Kernel 1: proj[M=32768, N=200] = concat(pre, wid)[M, 316] @ matrix[316, 200]
// ---------------------------------------------------------------------------
__global__ __launch_bounds__(NTHREADS) void proj_kernel(
    const float* __restrict__ pre,   // [32768, 300]
    const float* __restrict__ wid,   // [32768, 16]
    const float* __restrict__ mat)   // [316, 200]
{
    __shared__ float As[BK][BM + 4];   // transposed A tile, padded
    __shared__ float Bs[BK][BN];

    const int bm  = blockIdx.y * BM;
    const int bn  = blockIdx.x * BN;
    const int tid = threadIdx.x;
    const int row_t = (tid >> 4) * TM;   // 0..60
    const int col_t = (tid & 15) * TN;   // 0..60

    float acc[TM][TN];
#pragma unroll
    for (int i = 0; i < TM; i++)
#pragma unroll
        for (int j = 0; j < TN; j++) acc[i][j] = 0.0f;

    for (int kk = 0; kk < KIN; kk += BK) {
        // Load A tile: element (m, kl). Coalesced: 16 consecutive k per row.
#pragma unroll
        for (int j = 0; j < (BM * BK) / NTHREADS; j++) {
            int idx = tid + j * NTHREADS;
            int m   = idx >> 4;        // /16
            int kl  = idx & 15;
            int gk  = kk + kl;
            int gm  = bm + m;          // always < 32768 (32768 % 64 == 0)
            float v = 0.0f;
            if (gk < PRE_)       v = pre[gm * PRE_ + gk];
            else if (gk < KIN)   v = wid[gm * FLG_ + (gk - PRE_)];
            As[kl][m] = v;
        }
        // Load B tile: element (kl, n). matrix row-major [K, N]: contiguous n.
#pragma unroll
        for (int j = 0; j < (BK * BN) / NTHREADS; j++) {
            int idx = tid + j * NTHREADS;
            int n   = idx & 63;
            int kl  = idx >> 6;
            int gk  = kk + kl;
            int gn  = bn + n;
            float v = 0.0f;
            if (gk < KIN && gn < RD_) v = mat[gk * RD_ + gn];
            Bs[kl][n] = v;
        }
        __syncthreads();

#pragma unroll
        for (int k = 0; k < BK; k++) {
            float a[TM], b[TN];
#pragma unroll
            for (int i = 0; i < TM; i++) a[i] = As[k][row_t + i];
#pragma unroll
            for (int j = 0; j < TN; j++) b[j] = Bs[k][col_t + j];
#pragma unroll
            for (int i = 0; i < TM; i++)
#pragma unroll
                for (int j = 0; j < TN; j++)
                    acc[i][j] = fmaf(a[i], b[j], acc[i][j]);
        }
        __syncthreads();
    }

#pragma unroll
    for (int i = 0; i < TM; i++) {
        int gm = bm + row_t + i;
#pragma unroll
        for (int j = 0; j < TN; j++) {
            int gn = bn + col_t + j;
            if (gn < RD_) g_proj[gm * RD_ + gn] = acc[i][j];
        }
    }
}

// ---------------------------------------------------------------------------
// Kernel 2 (per batch z): scores[S, V] = proj_b[S, 200] @ roles_b[V, 200]^T
// NT GEMM: both operands K-contiguous. Fused col-1 zeroing + output write.
// ---------------------------------------------------------------------------
__global__ __launch_bounds__(NTHREADS) void score_kernel(
    const float* __restrict__ roles,  // [B, V*200]
    float* __restrict__ out)          // [B*S, V]
{
    __shared__ float As[BK][BM + 4];
    __shared__ float Bs[BK][BN + 1];

    const int b   = blockIdx.z;
    const float* A  = g_proj + (size_t)b * S_ * RD_;
    const float* Bb = roles  + (size_t)b * V_ * RD_;

    const int bm  = blockIdx.y * BM;
    const int bn  = blockIdx.x * BN;
    const int tid = threadIdx.x;
    const int row_t = (tid >> 4) * TM;
    const int col_t = (tid & 15) * TN;

    float acc[TM][TN];
#pragma unroll
    for (int i = 0; i < TM; i++)
#pragma unroll
        for (int j = 0; j < TN; j++) acc[i][j] = 0.0f;

    for (int kk = 0; kk < RD_; kk += BK) {
        // A tile: proj rows, k-contiguous -> coalesced
#pragma unroll
        for (int j = 0; j < (BM * BK) / NTHREADS; j++) {
            int idx = tid + j * NTHREADS;
            int m   = idx >> 4;
            int kl  = idx & 15;
            int gk  = kk + kl;
            float v = 0.0f;
            if (gk < RD_) v = A[(bm + m) * RD_ + gk];
            As[kl][m] = v;
        }
        // B tile: roles rows [V, 200], k-contiguous -> coalesced; store transposed
#pragma unroll
        for (int j = 0; j < (BN * BK) / NTHREADS; j++) {
            int idx = tid + j * NTHREADS;
            int n   = idx >> 4;
            int kl  = idx & 15;
            int gk  = kk + kl;
            int gn  = bn + n;
            float v = 0.0f;
            if (gk < RD_ && gn < V_) v = Bb[gn * RD_ + gk];
            Bs[kl][n] = v;
        }
        __syncthreads();

#pragma unroll
        for (int k = 0; k < BK; k++) {
            float a[TM], bb[TN];
#pragma unroll
            for (int i = 0; i < TM; i++) a[i] = As[k][row_t + i];
#pragma unroll
            for (int j = 0; j < TN; j++) bb[j] = Bs[k][col_t + j];
#pragma unroll
            for (int i = 0; i < TM; i++)
#pragma unroll
                for (int j = 0; j < TN; j++)
                    acc[i][j] = fmaf(a[i], bb[j], acc[i][j]);
        }
        __syncthreads();
    }

#pragma unroll
    for (int i = 0; i < TM; i++) {
        int gm = b * S_ + bm + row_t + i;   // global output row
#pragma unroll
        for (int j = 0; j < TN; j++) {
            int gn = bn + col_t + j;
            if (gn < V_) {
                float v = (gn == 1) ? 0.0f : acc[i][j];
                out[(size_t)gm * V_ + gn] = v;
            }
        }
    }
}

// ---------------------------------------------------------------------------
extern "C" void kernel_launch(void* const* d_in, const int* in_sizes, int n_in,
                              void* d_out, int out_size)
{
    const float* roles = (const float*)d_in[0];   // [32, 60000]
    const float* pre   = (const float*)d_in[1];   // [32, 1024, 300]
    const float* wid   = (const float*)d_in[2];   // [32, 1024, 16]
    const float* mat   = (const float*)d_in[3];   // [316, 200]
    float* out = (float*)d_out;                   // [32768, 300]

    // Kernel 1: proj GEMM. M = 32768, N = 200
    {
        dim3 grid((RD_ + BN - 1) / BN, (B_ * S_) / BM, 1);   // (4, 512)
        proj_kernel<<<grid, NTHREADS>>>(pre, wid, mat);
    }
    // Kernel 2: batched score GEMM. Per batch: M = 1024, N = 300
    {
        dim3 grid((V_ + BN - 1) / BN, S_ / BM, B_);          // (5, 16, 32)
        score_kernel<<<grid, NTHREADS>>>(roles, out);
    }
}

// round 4
// speedup vs baseline: 1.4503x; 1.4503x over previous
#include <cuda_runtime.h>

// Problem constants
#define B_   32
#define S_   1024
#define V_   300
#define KIN  316      // PRETRAIN(300) + FLAG(16)
#define PRE_ 300
#define FLG_ 16
#define RD_  200      // ROLE_D

// Tiling: 128x64 block tile, 8x4 microtile, 256 threads
#define BM 128
#define BN 64
#define BK 16
#define TM 8
#define TN 4
#define NTHREADS 256

// Scratch for proj: [B, S, RD] fp32 = 26.2 MB (static global, no alloc)
__device__ float g_proj[B_ * S_ * RD_];

// ---------------------------------------------------------------------------
// Kernel 1: proj[M=32768, N=200] = concat(pre, wid)[M, 316] @ matrix[316, 200]
// ---------------------------------------------------------------------------
__global__ __launch_bounds__(NTHREADS) void proj_kernel(
    const float* __restrict__ pre,   // [32768, 300]
    const float* __restrict__ wid,   // [32768, 16]
    const float* __restrict__ mat)   // [316, 200]
{
    __shared__ float As[BK][BM];   // k-major (transposed), rows 512B -> f4 aligned
    __shared__ float Bs[BK][BN];   // rows 256B -> f4 aligned

    const int bm  = blockIdx.y * BM;
    const int bn  = blockIdx.x * BN;
    const int tid = threadIdx.x;
    const int row_t = (tid >> 4) * TM;   // 0..120
    const int col_t = (tid & 15) * TN;   // 0..60

    float acc[TM][TN];
#pragma unroll
    for (int i = 0; i < TM; i++)
#pragma unroll
        for (int j = 0; j < TN; j++) acc[i][j] = 0.0f;

    for (int kk = 0; kk < KIN; kk += BK) {
        // ---- A tile: 128 x 16 = 512 float4 groups, 2 per thread ----
#pragma unroll
        for (int t = 0; t < 2; t++) {
            int idx = tid + t * NTHREADS;        // 0..511
            int m   = idx >> 2;                  // 0..127
            int k0  = (idx & 3) * 4;             // 0,4,8,12
            int gm  = bm + m;
            int gk  = kk + k0;
            float4 v = make_float4(0.f, 0.f, 0.f, 0.f);
            if (gk < PRE_)       v = *(const float4*)(pre + (size_t)gm * PRE_ + gk);
            else if (gk < KIN)   v = *(const float4*)(wid + (size_t)gm * FLG_ + (gk - PRE_));
            As[k0 + 0][m] = v.x;
            As[k0 + 1][m] = v.y;
            As[k0 + 2][m] = v.z;
            As[k0 + 3][m] = v.w;
        }
        // ---- B tile: 16 x 64 = 256 float4 groups, 1 per thread ----
        {
            int kl = tid >> 4;                   // 0..15
            int n0 = (tid & 15) * 4;             // 0..60
            int gk = kk + kl;
            int gn = bn + n0;
            float4 v = make_float4(0.f, 0.f, 0.f, 0.f);
            if (gk < KIN && gn < RD_)            // gn mult of 4, 200%4==0 -> full group
                v = *(const float4*)(mat + (size_t)gk * RD_ + gn);
            *(float4*)&Bs[kl][n0] = v;
        }
        __syncthreads();

#pragma unroll
        for (int k = 0; k < BK; k++) {
            float4 a0 = *(const float4*)&As[k][row_t];
            float4 a1 = *(const float4*)&As[k][row_t + 4];
            float4 b0 = *(const float4*)&Bs[k][col_t];
            float a[TM] = {a0.x, a0.y, a0.z, a0.w, a1.x, a1.y, a1.z, a1.w};
            float bb[TN] = {b0.x, b0.y, b0.z, b0.w};
#pragma unroll
            for (int i = 0; i < TM; i++)
#pragma unroll
                for (int j = 0; j < TN; j++)
                    acc[i][j] = fmaf(a[i], bb[j], acc[i][j]);
        }
        __syncthreads();
    }

    const int gn0 = bn + col_t;
    if (gn0 < RD_) {                              // mult of 4 -> whole group valid
#pragma unroll
        for (int i = 0; i < TM; i++) {
            int gm = bm + row_t + i;
            float4 r = make_float4(acc[i][0], acc[i][1], acc[i][2], acc[i][3]);
            *(float4*)&g_proj[(size_t)gm * RD_ + gn0] = r;
        }
    }
}

// ---------------------------------------------------------------------------
// Kernel 2 (per batch z): scores[S, V] = proj_b[S, 200] @ roles_b[V, 200]^T
// Fused col-1 zeroing + output write.
// ---------------------------------------------------------------------------
__global__ __launch_bounds__(NTHREADS) void score_kernel(
    const float* __restrict__ roles,  // [B, V*200]
    float* __restrict__ out)          // [B*S, V]
{
    __shared__ float As[BK][BM];
    __shared__ float Bs[BK][BN];

    const int b   = blockIdx.z;
    const float* A  = g_proj + (size_t)b * S_ * RD_;
    const float* Bb = roles  + (size_t)b * V_ * RD_;

    const int bm  = blockIdx.y * BM;
    const int bn  = blockIdx.x * BN;
    const int tid = threadIdx.x;
    const int row_t = (tid >> 4) * TM;
    const int col_t = (tid & 15) * TN;

    float acc[TM][TN];
#pragma unroll
    for (int i = 0; i < TM; i++)
#pragma unroll
        for (int j = 0; j < TN; j++) acc[i][j] = 0.0f;

    for (int kk = 0; kk < RD_; kk += BK) {
        // ---- A tile: 128 x 16 = 512 float4 groups, 2 per thread ----
#pragma unroll
        for (int t = 0; t < 2; t++) {
            int idx = tid + t * NTHREADS;
            int m   = idx >> 2;
            int k0  = (idx & 3) * 4;
            int gk  = kk + k0;
            float4 v = make_float4(0.f, 0.f, 0.f, 0.f);
            if (gk < RD_)
                v = *(const float4*)(A + (size_t)(bm + m) * RD_ + gk);
            As[k0 + 0][m] = v.x;
            As[k0 + 1][m] = v.y;
            As[k0 + 2][m] = v.z;
            As[k0 + 3][m] = v.w;
        }
        // ---- B tile: roles rows (k-contiguous), transposed store ----
        {
            int n  = tid >> 2;                   // 0..63
            int k0 = (tid & 3) * 4;
            int gn = bn + n;
            int gk = kk + k0;
            float4 v = make_float4(0.f, 0.f, 0.f, 0.f);
            if (gn < V_ && gk < RD_)
                v = *(const float4*)(Bb + (size_t)gn * RD_ + gk);
            Bs[k0 + 0][n] = v.x;
            Bs[k0 + 1][n] = v.y;
            Bs[k0 + 2][n] = v.z;
            Bs[k0 + 3][n] = v.w;
        }
        __syncthreads();

#pragma unroll
        for (int k = 0; k < BK; k++) {
            float4 a0 = *(const float4*)&As[k][row_t];
            float4 a1 = *(const float4*)&As[k][row_t + 4];
            float4 b0 = *(const float4*)&Bs[k][col_t];
            float a[TM] = {a0.x, a0.y, a0.z, a0.w, a1.x, a1.y, a1.z, a1.w};
            float bb[TN] = {b0.x, b0.y, b0.z, b0.w};
#pragma unroll
            for (int i = 0; i < TM; i++)
#pragma unroll
                for (int j = 0; j < TN; j++)
                    acc[i][j] = fmaf(a[i], bb[j], acc[i][j]);
        }
        __syncthreads();
    }

    const int gn0 = bn + col_t;
    if (gn0 < V_) {                               // mult of 4, 300%4==0 -> full group
#pragma unroll
        for (int i = 0; i < TM; i++) {
            int gm = b * S_ + bm + row_t + i;
            float v1 = (gn0 == 0) ? 0.0f : acc[i][1];   // zero column v==1
            float4 r = make_float4(acc[i][0], v1, acc[i][2], acc[i][3]);
            *(float4*)&out[(size_t)gm * V_ + gn0] = r;
        }
    }
}

// ---------------------------------------------------------------------------
extern "C" void kernel_launch(void* const* d_in, const int* in_sizes, int n_in,
                              void* d_out, int out_size)
{
    const float* roles = (const float*)d_in[0];   // [32, 60000]
    const float* pre   = (const float*)d_in[1];   // [32, 1024, 300]
    const float* wid   = (const float*)d_in[2];   // [32, 1024, 16]
    const float* mat   = (const float*)d_in[3];   // [316, 200]
    float* out = (float*)d_out;                   // [32768, 300]

    // Kernel 1: proj GEMM. M = 32768, N = 200
    {
        dim3 grid((RD_ + BN - 1) / BN, (B_ * S_) / BM, 1);   // (4, 256)
        proj_kernel<<<grid, NTHREADS>>>(pre, wid, mat);
    }
    // Kernel 2: batched score GEMM. Per batch: M = 1024, N = 300
    {
        dim3 grid((V_ + BN - 1) / BN, S_ / BM, B_);          // (5, 8, 32)
        score_kernel<<<grid, NTHREADS>>>(roles, out);
    }
}